// round 13
// baseline (speedup 1.0000x reference)
#include <cuda_runtime.h>
#include <cuda_fp16.h>
#include <math.h>
#include <stdint.h>

#define HH 256
#define WW 256
#define BB 4
#define CIN 128
#define NOC 128
#define NSTAGE 24                        // (8 cin-chunks of 16) x (3 dy)

#define A_WORDS 4096                     // per-stage U: [4 tap][8 blk][32 lane][4 e] fp16x2
#define V_STRIDE 40                      // words per (tap,pair) row: 32 tiles + 8 pad (bank-perfect)
#define V_WORDS (4 * 8 * V_STRIDE)       // 1280
#define BUF_BYTES ((A_WORDS + V_WORDS) * 4)      // 21504
#define AOFF(p) ((p) * BUF_BYTES)
#define VOFF(p) ((p) * BUF_BYTES + A_WORDS * 4)
#define DYN_BYTES (2 * BUF_BYTES)                // 43008

// ---------------- device scratch ----------------
__device__ uint32_t g_wA[NSTAGE * A_WORDS]; // Winograd-U, fragment-permuted fp16x2, BN-folded
__device__ float g_bfold[NOC];
__device__ float g_attw[NOC];
__device__ float g_att[2 * BB * HH * WW];

// ---------------- helpers ----------------
__device__ __forceinline__ uint32_t smem_u32(const void* p) {
    uint32_t a;
    asm("{ .reg .u64 t; cvta.to.shared.u64 t, %1; cvt.u32.u64 %0, t; }" : "=r"(a) : "l"(p));
    return a;
}
__device__ __forceinline__ uint32_t packh2(float a, float b) {
    __half2 h = __floats2half2_rn(a, b);
    return *reinterpret_cast<uint32_t*>(&h);
}
__device__ __forceinline__ void cp16(uint32_t dst, const void* src) {
    asm volatile("cp.async.cg.shared.global [%0], [%1], 16;" :: "r"(dst), "l"(src));
}
__device__ __forceinline__ void mma16(float* d, const uint32_t* a, uint32_t b0, uint32_t b1) {
    asm volatile(
        "mma.sync.aligned.m16n8k16.row.col.f32.f16.f16.f32 "
        "{%0,%1,%2,%3},{%4,%5,%6,%7},{%8,%9},{%0,%1,%2,%3};"
        : "+f"(d[0]), "+f"(d[1]), "+f"(d[2]), "+f"(d[3])
        : "r"(a[0]), "r"(a[1]), "r"(a[2]), "r"(a[3]), "r"(b0), "r"(b1));
}

// ---------------- kernel 0: BN fold + Winograd-U fp16 fragment tiles ----------------
// g_wA[s][tap][blk][lane][e]: oc = blk*16 + g + 8*(e&1); pair = tig + 4*(e>>1);
//   cin = (s/3)*16 + 2*pair + {0,1}; dy = s%3.
//   u0=w0, u1=(w0+w1+w2)/2, u2=(w0-w1+w2)/2, u3=w2 over the 3 dx taps.
__global__ void setup_kernel(
    const float* __restrict__ wa, const float* __restrict__ ba,
    const float* __restrict__ wb, const float* __restrict__ bb,
    const float* __restrict__ ga, const float* __restrict__ bta,
    const float* __restrict__ ma, const float* __restrict__ va,
    const float* __restrict__ gb, const float* __restrict__ btb,
    const float* __restrict__ mb, const float* __restrict__ vb,
    const float* __restrict__ attaw, const float* __restrict__ attbw)
{
    int idx = blockIdx.x * blockDim.x + threadIdx.x;
    if (idx < NOC) {
        int oc = idx;
        bool isa = oc < 64;
        int o = isa ? oc : oc - 64;
        float gamma = isa ? ga[o] : gb[o];
        float beta  = isa ? bta[o] : btb[o];
        float mean  = isa ? ma[o] : mb[o];
        float var   = isa ? va[o] : vb[o];
        float A = gamma / sqrtf(var + 1e-3f);
        float bias = isa ? ba[o] : bb[o];
        g_bfold[oc] = (bias - mean) * A + beta;
        g_attw[oc]  = isa ? attaw[o] : attbw[o];
    }
    if (idx < NSTAGE * A_WORDS) {
        int e    = idx & 3;
        int lane = (idx >> 2) & 31;
        int blk  = (idx >> 7) & 7;
        int tap  = (idx >> 10) & 3;
        int s    = idx / A_WORDS;
        int g    = lane >> 2;
        int tig  = lane & 3;
        int oc   = blk * 16 + g + ((e & 1) ? 8 : 0);
        int pair = tig + ((e & 2) ? 4 : 0);
        int cin0 = (s / 3) * 16 + 2 * pair;
        int dy   = s % 3;
        bool isa = oc < 64;
        int o = isa ? oc : oc - 64;
        float gamma = isa ? ga[o] : gb[o];
        float var   = isa ? va[o] : vb[o];
        float A = gamma / sqrtf(var + 1e-3f);
        const float* w = isa ? wa : wb;
        float u2v[2];
        #pragma unroll
        for (int lh = 0; lh < 2; lh++) {
            const float* wp = w + ((o * CIN + cin0 + lh) * 3 + dy) * 3;
            float w0 = wp[0] * A, w1 = wp[1] * A, w2 = wp[2] * A;
            float u;
            if      (tap == 0) u = w0;
            else if (tap == 1) u = 0.5f * (w0 + w1 + w2);
            else if (tap == 2) u = 0.5f * (w0 - w1 + w2);
            else               u = w2;
            u2v[lh] = u;
        }
        g_wA[idx] = packh2(u2v[0], u2v[1]);
    }
}

// ---------------- kernel 1: Winograd-x fp16 conv + BN + 1x1 attention logit ----------------
// grid (4, 256, 4) = (64-px window, row y, batch). 256 threads, 8 warps, 2 CTAs/SM.
// warp w: mwarp = w>>1 (oc0 = mwarp*32), nwarp = w&1 (tile0 = nwarp*16).
// D = 128oc x 32tiles x 4taps; K = 24 stages x 16 cin.
__global__ void __launch_bounds__(256, 2) conv_att_kernel(
    const float* __restrict__ x, float* __restrict__ out,
    const float* __restrict__ attaw, const float* __restrict__ attab,
    const float* __restrict__ attbw, const float* __restrict__ attbb,
    const float* __restrict__ abga, const float* __restrict__ abba,
    const float* __restrict__ abma, const float* __restrict__ abva,
    const float* __restrict__ abgb, const float* __restrict__ abbb,
    const float* __restrict__ abmb, const float* __restrict__ abvb)
{
    extern __shared__ __align__(16) char dyn[];
    const int tid  = threadIdx.x;
    const int b    = blockIdx.z;
    const int y    = blockIdx.y;
    const int c0   = blockIdx.x * 64;
    const int w    = tid >> 5;
    const int lane = tid & 31;
    const int g    = lane >> 2;
    const int tig  = lane & 3;
    const int mwarp = w >> 1;
    const int nwarp = w & 1;
    const int oc0  = mwarp * 32;
    const int tile0 = nwarp * 16;
    const int blk0 = mwarp * 2;
    const uint32_t dynb = smem_u32(dyn);

    float c[4][2][2][4];                 // [tap][mm][nn][frag]
    #pragma unroll
    for (int t4 = 0; t4 < 4; t4++)
        #pragma unroll
        for (int mm = 0; mm < 2; mm++)
            #pragma unroll
            for (int nn = 0; nn < 2; nn++)
                #pragma unroll
                for (int k = 0; k < 4; k++) c[t4][mm][nn][k] = 0.f;

    const int vp  = tid >> 5;            // cin pair 0..7
    const int vtl = tid & 31;            // tile 0..31

    // A stage copy: 1024 x 16B
    auto stage_A = [&](int s, int p) {
        const char* src = (const char*)(g_wA + (size_t)s * A_WORDS) + tid * 16;
        uint32_t dst = dynb + AOFF(p) + tid * 16;
        #pragma unroll
        for (int r = 0; r < 4; r++)
            cp16(dst + r * 4096, src + r * 4096);
        asm volatile("cp.async.commit_group;" ::: "memory");
    };
    // load raw d0..d3 for this thread's (pair, tile) for stage s
    auto load_d = [&](int s, float d0[4], float d1[4]) {
        int grow = y + (s % 3) - 1;
        if ((unsigned)grow < HH) {
            const float* xa = x + (((size_t)b * CIN + (s / 3) * 16 + 2 * vp) * HH + grow) * WW;
            const float* xb = xa + (size_t)HH * WW;
            int cbase = c0 + 2 * vtl - 1;
            #pragma unroll
            for (int k = 0; k < 4; k++) {
                int col = cbase + k;
                bool ok = (unsigned)col < WW;
                d0[k] = ok ? xa[col] : 0.f;
                d1[k] = ok ? xb[col] : 0.f;
            }
        } else {
            #pragma unroll
            for (int k = 0; k < 4; k++) { d0[k] = 0.f; d1[k] = 0.f; }
        }
    };
    // transform + pack + store V into buffer p
    auto store_V = [&](int p, const float d0[4], const float d1[4]) {
        uint32_t* Vs = (uint32_t*)(dyn + VOFF(p));
        float a0 = d0[0] - d0[2], a1 = d0[1] + d0[2], a2 = d0[2] - d0[1], a3 = d0[1] - d0[3];
        float b0 = d1[0] - d1[2], b1 = d1[1] + d1[2], b2 = d1[2] - d1[1], b3 = d1[1] - d1[3];
        Vs[(0 * 8 + vp) * V_STRIDE + vtl] = packh2(a0, b0);
        Vs[(1 * 8 + vp) * V_STRIDE + vtl] = packh2(a1, b1);
        Vs[(2 * 8 + vp) * V_STRIDE + vtl] = packh2(a2, b2);
        Vs[(3 * 8 + vp) * V_STRIDE + vtl] = packh2(a3, b3);
    };

    // ---- prologue: stage 0 ----
    {
        stage_A(0, 0);
        float d0[4], d1[4];
        load_d(0, d0, d1);
        store_V(0, d0, d1);
        asm volatile("cp.async.wait_group 0;" ::: "memory");
        __syncthreads();
    }

    // ---- main loop ----
    for (int s = 0; s < NSTAGE; s++) {
        const int p = s & 1;
        const bool pre = (s + 1 < NSTAGE);
        float d0[4], d1[4];

        if (pre) {
            stage_A(s + 1, p ^ 1);
            load_d(s + 1, d0, d1);
        }

        // ---- compute on buffer p ----
        {
            const uint4* As = (const uint4*)(dyn + AOFF(p));
            const uint32_t* Vs = (const uint32_t*)(dyn + VOFF(p));
            #pragma unroll
            for (int t4 = 0; t4 < 4; t4++) {
                uint32_t a[2][4];
                #pragma unroll
                for (int mm = 0; mm < 2; mm++) {
                    uint4 av = As[(t4 * 8 + blk0 + mm) * 32 + lane];
                    a[mm][0] = av.x; a[mm][1] = av.y; a[mm][2] = av.z; a[mm][3] = av.w;
                }
                #pragma unroll
                for (int nn = 0; nn < 2; nn++) {
                    int col = tile0 + nn * 8 + g;
                    uint32_t bb0 = Vs[(t4 * 8 + tig) * V_STRIDE + col];
                    uint32_t bb1 = Vs[(t4 * 8 + tig + 4) * V_STRIDE + col];
                    mma16(c[t4][0][nn], a[0], bb0, bb1);
                    mma16(c[t4][1][nn], a[1], bb0, bb1);
                }
            }
        }

        if (pre) store_V(p ^ 1, d0, d1);
        asm volatile("cp.async.wait_group 0;" ::: "memory");
        __syncthreads();
    }

    // ---------------- epilogue: output transform + BN bias + store + att ----------------
    float bf[2][2], aw[2][2];
    #pragma unroll
    for (int mm = 0; mm < 2; mm++)
        #pragma unroll
        for (int i2 = 0; i2 < 2; i2++) {
            int ocr = oc0 + mm * 16 + g + i2 * 8;
            bf[mm][i2] = g_bfold[ocr];
            aw[mm][i2] = g_attw[ocr];
        }

    float ap_loc[2][2][2];               // [nn][j][parity]
    #pragma unroll
    for (int nn = 0; nn < 2; nn++)
        #pragma unroll
        for (int j = 0; j < 2; j++) { ap_loc[nn][j][0] = 0.f; ap_loc[nn][j][1] = 0.f; }

    #pragma unroll
    for (int mm = 0; mm < 2; mm++)
        #pragma unroll
        for (int i2 = 0; i2 < 2; i2++) {
            int ocr = oc0 + mm * 16 + g + i2 * 8;
            float* orow = out + (((size_t)b * NOC + ocr) * HH + y) * WW;
            #pragma unroll
            for (int nn = 0; nn < 2; nn++)
                #pragma unroll
                for (int j = 0; j < 2; j++) {
                    float M0 = c[0][mm][nn][i2 * 2 + j];
                    float M1 = c[1][mm][nn][i2 * 2 + j];
                    float M2 = c[2][mm][nn][i2 * 2 + j];
                    float M3 = c[3][mm][nn][i2 * 2 + j];
                    float fe = M0 + M1 + M2 + bf[mm][i2];
                    float fo = M1 - M2 - M3 + bf[mm][i2];
                    int tileG = tile0 + nn * 8 + 2 * tig + j;
                    int px = c0 + 2 * tileG;
                    ap_loc[nn][j][0] = fmaf(aw[mm][i2], fe, ap_loc[nn][j][0]);
                    ap_loc[nn][j][1] = fmaf(aw[mm][i2], fo, ap_loc[nn][j][1]);
                    *(float2*)(orow + px) = make_float2(fe, fo);
                }
        }

    // reduce attention partials over g-lanes (xor 4/8/16 keeps tig), deterministic
    #pragma unroll
    for (int nn = 0; nn < 2; nn++)
        #pragma unroll
        for (int j = 0; j < 2; j++)
            #pragma unroll
            for (int e = 0; e < 2; e++) {
                float v = ap_loc[nn][j][e];
                v += __shfl_xor_sync(0xFFFFFFFF, v, 4);
                v += __shfl_xor_sync(0xFFFFFFFF, v, 8);
                v += __shfl_xor_sync(0xFFFFFFFF, v, 16);
                ap_loc[nn][j][e] = v;
            }
    float* att_part = (float*)dyn;       // [8 warps][32 px-local]; all smem reads done
    if (g == 0) {
        #pragma unroll
        for (int nn = 0; nn < 2; nn++)
            #pragma unroll
            for (int j = 0; j < 2; j++)
                #pragma unroll
                for (int e = 0; e < 2; e++)
                    att_part[w * 32 + (nn * 8 + 2 * tig + j) * 2 + e] = ap_loc[nn][j][e];
    }
    __syncthreads();

    if (tid < 128) {
        int branch = tid >> 6;           // 0: a (mwarp 0,1), 1: b (mwarp 2,3)
        int pxl = tid & 63;
        int nw = pxl >> 5, pxin = pxl & 31;
        float ssum = att_part[(branch * 4 + nw) * 32 + pxin]
                   + att_part[(branch * 4 + 2 + nw) * 32 + pxin];
        int xx = c0 + pxl;
        float gh = fabsf((float)y  - 127.5f) * (1.f / 128.f);
        float gw = fabsf((float)xx - 127.5f) * (1.f / 128.f);
        const float* awp = branch ? attbw : attaw;
        float pre = ssum + awp[64] * gh + awp[65] * gw + (branch ? attbb[0] : attab[0]);
        float gm = branch ? abgb[0] : abga[0];
        float bt = branch ? abbb[0] : abba[0];
        float mn = branch ? abmb[0] : abma[0];
        float vr = branch ? abvb[0] : abva[0];
        float av = (pre - mn) * gm / sqrtf(vr + 1e-5f) + bt;
        g_att[(((size_t)branch * BB + b) * HH + y) * WW + xx] = av;
    }
}

// ---------------- kernel 2: 3x3 attention conv + sigmoid + in-place gating ----------------
__global__ void __launch_bounds__(256) map_kernel(
    float* __restrict__ out,
    const float* __restrict__ wa, const float* __restrict__ wb,
    const float* __restrict__ s1, const float* __restrict__ s2)
{
    __shared__ float swa[36], swb[36];
    int t = threadIdx.y * 32 + threadIdx.x;
    if (t < 36) { swa[t] = wa[t]; swb[t] = wb[t]; }
    __syncthreads();

    int b   = blockIdx.z;
    int gy  = blockIdx.y * 8 + threadIdx.y;
    int gx4 = blockIdx.x * 128 + threadIdx.x * 4;

    const float prmax = 1.41421356237f * (127.5f / 128.f);
    const float prmin = 1.41421356237f * (0.5f / 128.f);
    const float prk = 2.f / (prmax - prmin);
    const float prc = 1.f - prmax * prk;

    float scl1 = s1[0], scl2 = s2[0];
    float mapa[4], mapb[4];
    #pragma unroll
    for (int p = 0; p < 4; p++) {
        int gx = gx4 + p;
        float sa = 0.f, sb = 0.f;
        #pragma unroll
        for (int rr = 0; rr < 3; rr++) {
            int yq = gy + rr - 1;
            if ((unsigned)yq >= HH) continue;
            #pragma unroll
            for (int ss = 0; ss < 3; ss++) {
                int xq = gx + ss - 1;
                if ((unsigned)xq >= WW) continue;
                float av = g_att[(((size_t)0 * BB + b) * HH + yq) * WW + xq];
                float bv = g_att[(((size_t)1 * BB + b) * HH + yq) * WW + xq];
                float gh = fabsf((float)yq - 127.5f) * (1.f / 128.f);
                float gw = fabsf((float)xq - 127.5f) * (1.f / 128.f);
                float pr = prk * sqrtf(gh * gh + gw * gw) + prc;
                int tap = rr * 3 + ss;
                sa += swa[tap] * av + swa[9 + tap] * gh + swa[18 + tap] * gw + swa[27 + tap] * pr;
                sb += swb[tap] * bv + swb[9 + tap] * gh + swb[18 + tap] * gw + swb[27 + tap] * pr;
            }
        }
        mapa[p] = scl1 / (1.f + expf(-sa));
        mapb[p] = scl2 / (1.f + expf(-sb));
    }

    size_t base = (((size_t)b * NOC) * HH + gy) * WW + gx4;
    #pragma unroll 4
    for (int oc = 0; oc < NOC; oc++) {
        float4 v = *(float4*)(out + base + (size_t)oc * HH * WW);
        if (oc < 64) { v.x *= mapa[0]; v.y *= mapa[1]; v.z *= mapa[2]; v.w *= mapa[3]; }
        else         { v.x *= mapb[0]; v.y *= mapb[1]; v.z *= mapb[2]; v.w *= mapb[3]; }
        *(float4*)(out + base + (size_t)oc * HH * WW) = v;
    }
}

// ---------------- launch ----------------
extern "C" void kernel_launch(void* const* d_in, const int* in_sizes, int n_in,
                              void* d_out, int out_size)
{
    const float* x     = (const float*)d_in[0];
    const float* caw   = (const float*)d_in[1];
    const float* cab   = (const float*)d_in[2];
    const float* cbw   = (const float*)d_in[3];
    const float* cbb   = (const float*)d_in[4];
    const float* bag   = (const float*)d_in[5];
    const float* babt  = (const float*)d_in[6];
    const float* bam   = (const float*)d_in[7];
    const float* bav   = (const float*)d_in[8];
    const float* bbg   = (const float*)d_in[9];
    const float* bbbt  = (const float*)d_in[10];
    const float* bbm   = (const float*)d_in[11];
    const float* bbv   = (const float*)d_in[12];
    const float* attaw = (const float*)d_in[13];
    const float* attab = (const float*)d_in[14];
    const float* attbw = (const float*)d_in[15];
    const float* attbb = (const float*)d_in[16];
    const float* abga  = (const float*)d_in[17];
    const float* abba  = (const float*)d_in[18];
    const float* abma  = (const float*)d_in[19];
    const float* abva  = (const float*)d_in[20];
    const float* abgb  = (const float*)d_in[21];
    const float* abbb  = (const float*)d_in[22];
    const float* abmb  = (const float*)d_in[23];
    const float* abvb  = (const float*)d_in[24];
    const float* anaw  = (const float*)d_in[25];
    const float* anbw  = (const float*)d_in[26];
    const float* s1    = (const float*)d_in[27];
    const float* s2    = (const float*)d_in[28];
    float* out = (float*)d_out;

    cudaFuncSetAttribute(conv_att_kernel,
                         cudaFuncAttributeMaxDynamicSharedMemorySize, DYN_BYTES);

    setup_kernel<<<(NSTAGE * A_WORDS + 255) / 256, 256>>>(
        caw, cab, cbw, cbb,
        bag, babt, bam, bav, bbg, bbbt, bbm, bbv,
        attaw, attbw);

    conv_att_kernel<<<dim3(4, HH, BB), 256, DYN_BYTES>>>(
        x, out, attaw, attab, attbw, attbb,
        abga, abba, abma, abva, abgb, abbb, abmb, abvb);

    map_kernel<<<dim3(WW / 128, HH / 8, BB), dim3(32, 8)>>>(
        out, anaw, anbw, s1, s2);
}

// round 15
// speedup vs baseline: 1.1350x; 1.1350x over previous
#include <cuda_runtime.h>
#include <cuda_fp16.h>
#include <math.h>
#include <stdint.h>

#define HH 256
#define WW 256
#define BB 4
#define CIN 128
#define NOC 128
#define NSTAGE 24                        // (8 cin-chunks of 16) x (3 dy)

#define A_FLOATS 6144                    // per-stage fragment-permuted A
#define X_STRIDE 136
#define X_FLOATS (16 * X_STRIDE)         // 2176
#define AOFF(p) ((p) * A_FLOATS * 4)
#define XOFF(p) (2 * A_FLOATS * 4 + (p) * X_FLOATS * 4)
#define DYN_BYTES (2 * A_FLOATS * 4 + 2 * X_FLOATS * 4)   // 66560

// ---------------- device scratch ----------------
__device__ float g_wA[NSTAGE * A_FLOATS]; // fragment-permuted, tf32-rounded, BN-folded
__device__ float g_bfold[NOC];
__device__ float g_attw[NOC];
__device__ float g_att[2 * BB * HH * WW];
__device__ __half g_fh[(size_t)BB * NOC * HH * WW];  // fp16 f scratch (64 MB, L2-resident)

// ---------------- helpers ----------------
__device__ __forceinline__ uint32_t smem_u32(const void* p) {
    uint32_t a;
    asm("{ .reg .u64 t; cvta.to.shared.u64 t, %1; cvt.u32.u64 %0, t; }" : "=r"(a) : "l"(p));
    return a;
}
__device__ __forceinline__ uint32_t f2tf32(float f) {
    uint32_t r; asm("cvt.rna.tf32.f32 %0, %1;" : "=r"(r) : "f"(f)); return r;
}
__device__ __forceinline__ void cp16(uint32_t dst, const void* src) {
    asm volatile("cp.async.cg.shared.global [%0], [%1], 16;" :: "r"(dst), "l"(src));
}
__device__ __forceinline__ void mma8(float* d, const uint32_t* a, uint32_t b0, uint32_t b1) {
    asm volatile(
        "mma.sync.aligned.m16n8k8.row.col.f32.tf32.tf32.f32 "
        "{%0,%1,%2,%3},{%4,%5,%6,%7},{%8,%9},{%0,%1,%2,%3};"
        : "+f"(d[0]), "+f"(d[1]), "+f"(d[2]), "+f"(d[3])
        : "r"(a[0]), "r"(a[1]), "r"(a[2]), "r"(a[3]), "r"(b0), "r"(b1));
}

// ---------------- kernel 0: BN fold + fragment-permuted tf32 weight tiles ----------------
__global__ void setup_kernel(
    const float* __restrict__ wa, const float* __restrict__ ba,
    const float* __restrict__ wb, const float* __restrict__ bb,
    const float* __restrict__ ga, const float* __restrict__ bta,
    const float* __restrict__ ma, const float* __restrict__ va,
    const float* __restrict__ gb, const float* __restrict__ btb,
    const float* __restrict__ mb, const float* __restrict__ vb,
    const float* __restrict__ attaw, const float* __restrict__ attbw)
{
    int idx = blockIdx.x * blockDim.x + threadIdx.x;
    if (idx < NOC) {
        int oc = idx;
        bool isa = oc < 64;
        int o = isa ? oc : oc - 64;
        float gamma = isa ? ga[o] : gb[o];
        float beta  = isa ? bta[o] : btb[o];
        float mean  = isa ? ma[o] : mb[o];
        float var   = isa ? va[o] : vb[o];
        float A = gamma / sqrtf(var + 1e-3f);
        float bias = isa ? ba[o] : bb[o];
        g_bfold[oc] = (bias - mean) * A + beta;
        g_attw[oc]  = isa ? attaw[o] : attbw[o];
    }
    if (idx < NSTAGE * A_FLOATS) {
        int e    = idx & 3;
        int lane = (idx >> 2) & 31;
        int blk  = (idx >> 7) & 7;
        int kc   = (idx >> 10) % 6;
        int s    = idx / A_FLOATS;
        int g    = lane >> 2;
        int tig  = lane & 3;
        int oc = blk * 16 + g + ((e & 1) ? 8 : 0);
        int kl = tig + ((e & 2) ? 4 : 0);
        int cl = (kc & 1) * 8 + kl;
        int dxi = kc >> 1;
        int cin = (s / 3) * 16 + cl;
        int dy  = s % 3;
        bool isa = oc < 64;
        int o = isa ? oc : oc - 64;
        float gamma = isa ? ga[o] : gb[o];
        float var   = isa ? va[o] : vb[o];
        float A = gamma / sqrtf(var + 1e-3f);
        const float* w = isa ? wa : wb;
        float v = w[((o * CIN + cin) * 3 + dy) * 3 + dxi] * A;
        g_wA[idx] = __uint_as_float(f2tf32(v));
    }
}

// ---------------- kernel 1: mma.sync tf32 conv + BN + 1x1 attention logit ----------------
// grid (2, 256, 4) = (col half, row y, batch). 256 threads, 8 warps, 2 CTAs/SM.
// warp w: oc0 = (w>>1)*32, pix0 = (w&1)*64. D = 128oc x 128pix, K = 24 stages x 48.
__global__ void __launch_bounds__(256, 2) conv_att_kernel(
    const float* __restrict__ x,
    const float* __restrict__ attaw, const float* __restrict__ attab,
    const float* __restrict__ attbw, const float* __restrict__ attbb,
    const float* __restrict__ abga, const float* __restrict__ abba,
    const float* __restrict__ abma, const float* __restrict__ abva,
    const float* __restrict__ abgb, const float* __restrict__ abbb,
    const float* __restrict__ abmb, const float* __restrict__ abvb)
{
    extern __shared__ __align__(16) char dyn[];
    const int tid  = threadIdx.x;
    const int b    = blockIdx.z;
    const int y    = blockIdx.y;
    const int c0   = blockIdx.x * 128;
    const int w    = tid >> 5;
    const int lane = tid & 31;
    const int g    = lane >> 2;
    const int tig  = lane & 3;
    const int oc0  = (w >> 1) * 32;
    const int pix0 = (w & 1) * 64;
    const int blk0 = (w >> 1) * 2;
    const uint32_t dynb = smem_u32(dyn);

    float c[2][8][4];
    #pragma unroll
    for (int mm = 0; mm < 2; mm++)
        #pragma unroll
        for (int nn = 0; nn < 8; nn++)
            #pragma unroll
            for (int k = 0; k < 4; k++) c[mm][nn][k] = 0.f;

    const int cc = tid >> 4, l16 = tid & 15;   // x staging: 16 rows x 16 threads

    // ---- prologue: stage s=0 into buffer 0 ----
    {
        const char* src = (const char*)(g_wA) + tid * 16;
        #pragma unroll
        for (int r = 0; r < 6; r++)
            cp16(dynb + AOFF(0) + tid * 16 + r * 4096, src + r * 4096);
        asm volatile("cp.async.commit_group;" ::: "memory");

        float xr[9];
        int grow = y - 1;
        if ((unsigned)grow < HH) {
            const float* xb = x + (((size_t)b * CIN + cc) * HH + grow) * WW;
            #pragma unroll
            for (int i = 0; i < 9; i++) {
                int j = l16 + i * 16;
                int col = c0 - 1 + j;
                xr[i] = (j < 130 && (unsigned)col < WW) ? xb[col] : 0.f;
            }
        } else {
            #pragma unroll
            for (int i = 0; i < 9; i++) xr[i] = 0.f;
        }
        float* Xs = (float*)(dyn + XOFF(0));
        #pragma unroll
        for (int i = 0; i < 9; i++) {
            int j = l16 + i * 16;
            if (j < 130) Xs[cc * X_STRIDE + j] = __uint_as_float(f2tf32(xr[i]));
        }
        asm volatile("cp.async.wait_group 0;" ::: "memory");
        __syncthreads();
    }

    // ---- main loop ----
    for (int s = 0; s < NSTAGE; s++) {
        const int p = s & 1;
        const bool pre = (s + 1 < NSTAGE);
        float xr[9];

        if (pre) {
            const char* src = (const char*)(g_wA + (s + 1) * A_FLOATS) + tid * 16;
            #pragma unroll
            for (int r = 0; r < 6; r++)
                cp16(dynb + AOFF(p ^ 1) + tid * 16 + r * 4096, src + r * 4096);
            asm volatile("cp.async.commit_group;" ::: "memory");
            int sn = s + 1;
            int grow = y + (sn % 3) - 1;
            if ((unsigned)grow < HH) {
                const float* xb = x + (((size_t)b * CIN + (sn / 3) * 16 + cc) * HH + grow) * WW;
                #pragma unroll
                for (int i = 0; i < 9; i++) {
                    int j = l16 + i * 16;
                    int col = c0 - 1 + j;
                    xr[i] = (j < 130 && (unsigned)col < WW) ? xb[col] : 0.f;
                }
            } else {
                #pragma unroll
                for (int i = 0; i < 9; i++) xr[i] = 0.f;
            }
        }

        // ---- compute on buffer p ----
        {
            const float4* As = (const float4*)(dyn + AOFF(p));
            const float* Xs = (const float*)(dyn + XOFF(p));
            #pragma unroll
            for (int kc = 0; kc < 6; kc++) {
                const int dxi = kc >> 1;
                const int c0k = (kc & 1) * 8;
                uint32_t a[2][4];
                #pragma unroll
                for (int mm = 0; mm < 2; mm++) {
                    float4 av = As[(kc * 8 + blk0 + mm) * 32 + lane];
                    a[mm][0] = __float_as_uint(av.x);
                    a[mm][1] = __float_as_uint(av.y);
                    a[mm][2] = __float_as_uint(av.z);
                    a[mm][3] = __float_as_uint(av.w);
                }
                #pragma unroll
                for (int nn = 0; nn < 8; nn++) {
                    const float* bp = Xs + (c0k + tig) * X_STRIDE + pix0 + nn * 8 + g + dxi;
                    uint32_t b0 = __float_as_uint(bp[0]);
                    uint32_t b1 = __float_as_uint(bp[4 * X_STRIDE]);
                    mma8(c[0][nn], a[0], b0, b1);
                    mma8(c[1][nn], a[1], b0, b1);
                }
            }
        }

        if (pre) {
            float* Xs = (float*)(dyn + XOFF(p ^ 1));
            #pragma unroll
            for (int i = 0; i < 9; i++) {
                int j = l16 + i * 16;
                if (j < 130) Xs[cc * X_STRIDE + j] = __uint_as_float(f2tf32(xr[i]));
            }
        }
        asm volatile("cp.async.wait_group 0;" ::: "memory");
        __syncthreads();
    }

    // ---------------- epilogue ----------------
    float bf[2][2], aw[2][2];
    #pragma unroll
    for (int mm = 0; mm < 2; mm++)
        #pragma unroll
        for (int i2 = 0; i2 < 2; i2++) {
            int ocr = oc0 + mm * 16 + g + i2 * 8;
            bf[mm][i2] = g_bfold[ocr];
            aw[mm][i2] = g_attw[ocr];
        }

    float ap_loc[8][2];
    #pragma unroll
    for (int nn = 0; nn < 8; nn++) { ap_loc[nn][0] = 0.f; ap_loc[nn][1] = 0.f; }

    #pragma unroll
    for (int mm = 0; mm < 2; mm++)
        #pragma unroll
        for (int i2 = 0; i2 < 2; i2++) {
            int ocr = oc0 + mm * 16 + g + i2 * 8;
            __half* orow = g_fh + (((size_t)b * NOC + ocr) * HH + y) * WW + c0 + pix0 + 2 * tig;
            #pragma unroll
            for (int nn = 0; nn < 8; nn++) {
                float f0 = c[mm][nn][i2 * 2 + 0] + bf[mm][i2];
                float f1 = c[mm][nn][i2 * 2 + 1] + bf[mm][i2];
                ap_loc[nn][0] = fmaf(aw[mm][i2], f0, ap_loc[nn][0]);
                ap_loc[nn][1] = fmaf(aw[mm][i2], f1, ap_loc[nn][1]);
                *(__half2*)(orow + nn * 8) = __floats2half2_rn(f0, f1);
            }
        }

    // reduce attention partials over g-lanes (same tig), deterministic butterfly
    #pragma unroll
    for (int nn = 0; nn < 8; nn++)
        #pragma unroll
        for (int j = 0; j < 2; j++) {
            float v = ap_loc[nn][j];
            v += __shfl_xor_sync(0xFFFFFFFF, v, 4);
            v += __shfl_xor_sync(0xFFFFFFFF, v, 8);
            v += __shfl_xor_sync(0xFFFFFFFF, v, 16);
            ap_loc[nn][j] = v;
        }
    float* att_part = (float*)dyn;   // A buf0 region, free now
    if (g == 0) {
        #pragma unroll
        for (int nn = 0; nn < 8; nn++) {
            att_part[w * 64 + nn * 8 + 2 * tig + 0] = ap_loc[nn][0];
            att_part[w * 64 + nn * 8 + 2 * tig + 1] = ap_loc[nn][1];
        }
    }
    __syncthreads();

    {
        int branch = tid >> 7;
        int pix = tid & 127;
        int nh = pix >> 6, pl = pix & 63;
        float ssum = att_part[(4 * branch + nh) * 64 + pl]
                   + att_part[(4 * branch + 2 + nh) * 64 + pl];
        int xx = c0 + pix;
        float gh = fabsf((float)y  - 127.5f) * (1.f / 128.f);
        float gw = fabsf((float)xx - 127.5f) * (1.f / 128.f);
        const float* awp = branch ? attbw : attaw;
        float pre = ssum + awp[64] * gh + awp[65] * gw + (branch ? attbb[0] : attab[0]);
        float gm = branch ? abgb[0] : abga[0];
        float bt = branch ? abbb[0] : abba[0];
        float mn = branch ? abmb[0] : abma[0];
        float vr = branch ? abvb[0] : abva[0];
        float av = (pre - mn) * gm / sqrtf(vr + 1e-5f) + bt;
        g_att[(((size_t)branch * BB + b) * HH + y) * WW + xx] = av;
    }
}

// ---------------- kernel 2: 3x3 attention conv + sigmoid + gated store ----------------
__global__ void __launch_bounds__(256) map_kernel(
    float* __restrict__ out,
    const float* __restrict__ wa, const float* __restrict__ wb,
    const float* __restrict__ s1, const float* __restrict__ s2)
{
    __shared__ float swa[36], swb[36];
    int t = threadIdx.y * 32 + threadIdx.x;
    if (t < 36) { swa[t] = wa[t]; swb[t] = wb[t]; }
    __syncthreads();

    int b   = blockIdx.z;
    int gy  = blockIdx.y * 8 + threadIdx.y;
    int gx4 = blockIdx.x * 128 + threadIdx.x * 4;

    const float prmax = 1.41421356237f * (127.5f / 128.f);
    const float prmin = 1.41421356237f * (0.5f / 128.f);
    const float prk = 2.f / (prmax - prmin);
    const float prc = 1.f - prmax * prk;

    float scl1 = s1[0], scl2 = s2[0];
    float mapa[4], mapb[4];
    #pragma unroll
    for (int p = 0; p < 4; p++) {
        int gx = gx4 + p;
        float sa = 0.f, sb = 0.f;
        #pragma unroll
        for (int rr = 0; rr < 3; rr++) {
            int yq = gy + rr - 1;
            if ((unsigned)yq >= HH) continue;
            #pragma unroll
            for (int ss = 0; ss < 3; ss++) {
                int xq = gx + ss - 1;
                if ((unsigned)xq >= WW) continue;
                float av = g_att[(((size_t)0 * BB + b) * HH + yq) * WW + xq];
                float bv = g_att[(((size_t)1 * BB + b) * HH + yq) * WW + xq];
                float gh = fabsf((float)yq - 127.5f) * (1.f / 128.f);
                float gw = fabsf((float)xq - 127.5f) * (1.f / 128.f);
                float pr = prk * sqrtf(gh * gh + gw * gw) + prc;
                int tap = rr * 3 + ss;
                sa += swa[tap] * av + swa[9 + tap] * gh + swa[18 + tap] * gw + swa[27 + tap] * pr;
                sb += swb[tap] * bv + swb[9 + tap] * gh + swb[18 + tap] * gw + swb[27 + tap] * pr;
            }
        }
        mapa[p] = scl1 / (1.f + expf(-sa));
        mapb[p] = scl2 / (1.f + expf(-sb));
    }

    size_t base = (((size_t)b * NOC) * HH + gy) * WW + gx4;
    #pragma unroll 4
    for (int oc = 0; oc < NOC; oc++) {
        const __half2* fp = (const __half2*)(g_fh + base + (size_t)oc * HH * WW);
        float2 h0 = __half22float2(fp[0]);
        float2 h1 = __half22float2(fp[1]);
        float4 v;
        if (oc < 64) {
            v.x = h0.x * mapa[0]; v.y = h0.y * mapa[1];
            v.z = h1.x * mapa[2]; v.w = h1.y * mapa[3];
        } else {
            v.x = h0.x * mapb[0]; v.y = h0.y * mapb[1];
            v.z = h1.x * mapb[2]; v.w = h1.y * mapb[3];
        }
        *(float4*)(out + base + (size_t)oc * HH * WW) = v;
    }
}

// ---------------- launch ----------------
extern "C" void kernel_launch(void* const* d_in, const int* in_sizes, int n_in,
                              void* d_out, int out_size)
{
    const float* x     = (const float*)d_in[0];
    const float* caw   = (const float*)d_in[1];
    const float* cab   = (const float*)d_in[2];
    const float* cbw   = (const float*)d_in[3];
    const float* cbb   = (const float*)d_in[4];
    const float* bag   = (const float*)d_in[5];
    const float* babt  = (const float*)d_in[6];
    const float* bam   = (const float*)d_in[7];
    const float* bav   = (const float*)d_in[8];
    const float* bbg   = (const float*)d_in[9];
    const float* bbbt  = (const float*)d_in[10];
    const float* bbm   = (const float*)d_in[11];
    const float* bbv   = (const float*)d_in[12];
    const float* attaw = (const float*)d_in[13];
    const float* attab = (const float*)d_in[14];
    const float* attbw = (const float*)d_in[15];
    const float* attbb = (const float*)d_in[16];
    const float* abga  = (const float*)d_in[17];
    const float* abba  = (const float*)d_in[18];
    const float* abma  = (const float*)d_in[19];
    const float* abva  = (const float*)d_in[20];
    const float* abgb  = (const float*)d_in[21];
    const float* abbb  = (const float*)d_in[22];
    const float* abmb  = (const float*)d_in[23];
    const float* abvb  = (const float*)d_in[24];
    const float* anaw  = (const float*)d_in[25];
    const float* anbw  = (const float*)d_in[26];
    const float* s1    = (const float*)d_in[27];
    const float* s2    = (const float*)d_in[28];
    float* out = (float*)d_out;

    cudaFuncSetAttribute(conv_att_kernel,
                         cudaFuncAttributeMaxDynamicSharedMemorySize, DYN_BYTES);

    setup_kernel<<<(NSTAGE * A_FLOATS + 255) / 256, 256>>>(
        caw, cab, cbw, cbb,
        bag, babt, bam, bav, bbg, bbbt, bbm, bbv,
        attaw, attbw);

    conv_att_kernel<<<dim3(2, HH, BB), 256, DYN_BYTES>>>(
        x, attaw, attab, attbw, attbb,
        abga, abba, abma, abva, abgb, abbb, abmb, abvb);

    map_kernel<<<dim3(WW / 128, HH / 8, BB), dim3(32, 8)>>>(
        out, anaw, anbw, s1, s2);
}

// round 16
// speedup vs baseline: 1.1441x; 1.0080x over previous
#include <cuda_runtime.h>
#include <cuda_fp16.h>
#include <math.h>
#include <stdint.h>

#define HH 256
#define WW 256
#define BB 4
#define CIN 128
#define NOC 128
#define NSTAGE 24                        // (8 cin-chunks of 16) x (3 dy)

#define A_FLOATS 6144                    // per-stage fragment-permuted A
#define X_STRIDE 136
#define X_FLOATS (16 * X_STRIDE)         // 2176
#define AOFF(p) ((p) * A_FLOATS * 4)
#define XOFF(p) (2 * A_FLOATS * 4 + (p) * X_FLOATS * 4)
#define DYN_BYTES (2 * A_FLOATS * 4 + 2 * X_FLOATS * 4)   // 66560

#define HS_STRIDE 136                    // halves per oc row in epilogue smem tile (272B, 16B-mult)

// ---------------- device scratch ----------------
__device__ float g_wA[NSTAGE * A_FLOATS]; // fragment-permuted, tf32-rounded, BN-folded
__device__ float g_bfold[NOC];
__device__ float g_attw[NOC];
__device__ float g_att[2 * BB * HH * WW];
__device__ __align__(16) __half g_fh[(size_t)BB * NOC * HH * WW];  // fp16 f scratch (64 MB)

// ---------------- helpers ----------------
__device__ __forceinline__ uint32_t smem_u32(const void* p) {
    uint32_t a;
    asm("{ .reg .u64 t; cvta.to.shared.u64 t, %1; cvt.u32.u64 %0, t; }" : "=r"(a) : "l"(p));
    return a;
}
__device__ __forceinline__ uint32_t f2tf32(float f) {
    uint32_t r; asm("cvt.rna.tf32.f32 %0, %1;" : "=r"(r) : "f"(f)); return r;
}
__device__ __forceinline__ void cp16(uint32_t dst, const void* src) {
    asm volatile("cp.async.cg.shared.global [%0], [%1], 16;" :: "r"(dst), "l"(src));
}
__device__ __forceinline__ void mma8(float* d, const uint32_t* a, uint32_t b0, uint32_t b1) {
    asm volatile(
        "mma.sync.aligned.m16n8k8.row.col.f32.tf32.tf32.f32 "
        "{%0,%1,%2,%3},{%4,%5,%6,%7},{%8,%9},{%0,%1,%2,%3};"
        : "+f"(d[0]), "+f"(d[1]), "+f"(d[2]), "+f"(d[3])
        : "r"(a[0]), "r"(a[1]), "r"(a[2]), "r"(a[3]), "r"(b0), "r"(b1));
}

// ---------------- kernel 0: BN fold + fragment-permuted tf32 weight tiles ----------------
__global__ void setup_kernel(
    const float* __restrict__ wa, const float* __restrict__ ba,
    const float* __restrict__ wb, const float* __restrict__ bb,
    const float* __restrict__ ga, const float* __restrict__ bta,
    const float* __restrict__ ma, const float* __restrict__ va,
    const float* __restrict__ gb, const float* __restrict__ btb,
    const float* __restrict__ mb, const float* __restrict__ vb,
    const float* __restrict__ attaw, const float* __restrict__ attbw)
{
    int idx = blockIdx.x * blockDim.x + threadIdx.x;
    if (idx < NOC) {
        int oc = idx;
        bool isa = oc < 64;
        int o = isa ? oc : oc - 64;
        float gamma = isa ? ga[o] : gb[o];
        float beta  = isa ? bta[o] : btb[o];
        float mean  = isa ? ma[o] : mb[o];
        float var   = isa ? va[o] : vb[o];
        float A = gamma / sqrtf(var + 1e-3f);
        float bias = isa ? ba[o] : bb[o];
        g_bfold[oc] = (bias - mean) * A + beta;
        g_attw[oc]  = isa ? attaw[o] : attbw[o];
    }
    if (idx < NSTAGE * A_FLOATS) {
        int e    = idx & 3;
        int lane = (idx >> 2) & 31;
        int blk  = (idx >> 7) & 7;
        int kc   = (idx >> 10) % 6;
        int s    = idx / A_FLOATS;
        int g    = lane >> 2;
        int tig  = lane & 3;
        int oc = blk * 16 + g + ((e & 1) ? 8 : 0);
        int kl = tig + ((e & 2) ? 4 : 0);
        int cl = (kc & 1) * 8 + kl;
        int dxi = kc >> 1;
        int cin = (s / 3) * 16 + cl;
        int dy  = s % 3;
        bool isa = oc < 64;
        int o = isa ? oc : oc - 64;
        float gamma = isa ? ga[o] : gb[o];
        float var   = isa ? va[o] : vb[o];
        float A = gamma / sqrtf(var + 1e-3f);
        const float* w = isa ? wa : wb;
        float v = w[((o * CIN + cin) * 3 + dy) * 3 + dxi] * A;
        g_wA[idx] = __uint_as_float(f2tf32(v));
    }
}

// ---------------- kernel 1: mma.sync tf32 conv + BN + 1x1 attention logit ----------------
// grid (2, 256, 4) = (col half, row y, batch). 256 threads, 8 warps, 2 CTAs/SM.
__global__ void __launch_bounds__(256, 2) conv_att_kernel(
    const float* __restrict__ x,
    const float* __restrict__ attaw, const float* __restrict__ attab,
    const float* __restrict__ attbw, const float* __restrict__ attbb,
    const float* __restrict__ abga, const float* __restrict__ abba,
    const float* __restrict__ abma, const float* __restrict__ abva,
    const float* __restrict__ abgb, const float* __restrict__ abbb,
    const float* __restrict__ abmb, const float* __restrict__ abvb)
{
    extern __shared__ __align__(16) char dyn[];
    const int tid  = threadIdx.x;
    const int b    = blockIdx.z;
    const int y    = blockIdx.y;
    const int c0   = blockIdx.x * 128;
    const int w    = tid >> 5;
    const int lane = tid & 31;
    const int g    = lane >> 2;
    const int tig  = lane & 3;
    const int oc0  = (w >> 1) * 32;
    const int pix0 = (w & 1) * 64;
    const int blk0 = (w >> 1) * 2;
    const uint32_t dynb = smem_u32(dyn);

    float c[2][8][4];
    #pragma unroll
    for (int mm = 0; mm < 2; mm++)
        #pragma unroll
        for (int nn = 0; nn < 8; nn++)
            #pragma unroll
            for (int k = 0; k < 4; k++) c[mm][nn][k] = 0.f;

    const int cc = tid >> 4, l16 = tid & 15;   // x staging: 16 rows x 16 threads

    // ---- prologue: stage s=0 into buffer 0 ----
    {
        const char* src = (const char*)(g_wA) + tid * 16;
        #pragma unroll
        for (int r = 0; r < 6; r++)
            cp16(dynb + AOFF(0) + tid * 16 + r * 4096, src + r * 4096);
        asm volatile("cp.async.commit_group;" ::: "memory");

        float xr[9];
        int grow = y - 1;
        if ((unsigned)grow < HH) {
            const float* xb = x + (((size_t)b * CIN + cc) * HH + grow) * WW;
            #pragma unroll
            for (int i = 0; i < 9; i++) {
                int j = l16 + i * 16;
                int col = c0 - 1 + j;
                xr[i] = (j < 130 && (unsigned)col < WW) ? xb[col] : 0.f;
            }
        } else {
            #pragma unroll
            for (int i = 0; i < 9; i++) xr[i] = 0.f;
        }
        float* Xs = (float*)(dyn + XOFF(0));
        #pragma unroll
        for (int i = 0; i < 9; i++) {
            int j = l16 + i * 16;
            if (j < 130) Xs[cc * X_STRIDE + j] = __uint_as_float(f2tf32(xr[i]));
        }
        asm volatile("cp.async.wait_group 0;" ::: "memory");
        __syncthreads();
    }

    // ---- main loop ----
    for (int s = 0; s < NSTAGE; s++) {
        const int p = s & 1;
        const bool pre = (s + 1 < NSTAGE);
        float xr[9];

        if (pre) {
            const char* src = (const char*)(g_wA + (s + 1) * A_FLOATS) + tid * 16;
            #pragma unroll
            for (int r = 0; r < 6; r++)
                cp16(dynb + AOFF(p ^ 1) + tid * 16 + r * 4096, src + r * 4096);
            asm volatile("cp.async.commit_group;" ::: "memory");
            int sn = s + 1;
            int grow = y + (sn % 3) - 1;
            if ((unsigned)grow < HH) {
                const float* xb = x + (((size_t)b * CIN + (sn / 3) * 16 + cc) * HH + grow) * WW;
                #pragma unroll
                for (int i = 0; i < 9; i++) {
                    int j = l16 + i * 16;
                    int col = c0 - 1 + j;
                    xr[i] = (j < 130 && (unsigned)col < WW) ? xb[col] : 0.f;
                }
            } else {
                #pragma unroll
                for (int i = 0; i < 9; i++) xr[i] = 0.f;
            }
        }

        // ---- compute on buffer p ----
        {
            const float4* As = (const float4*)(dyn + AOFF(p));
            const float* Xs = (const float*)(dyn + XOFF(p));
            #pragma unroll
            for (int kc = 0; kc < 6; kc++) {
                const int dxi = kc >> 1;
                const int c0k = (kc & 1) * 8;
                uint32_t a[2][4];
                #pragma unroll
                for (int mm = 0; mm < 2; mm++) {
                    float4 av = As[(kc * 8 + blk0 + mm) * 32 + lane];
                    a[mm][0] = __float_as_uint(av.x);
                    a[mm][1] = __float_as_uint(av.y);
                    a[mm][2] = __float_as_uint(av.z);
                    a[mm][3] = __float_as_uint(av.w);
                }
                #pragma unroll
                for (int nn = 0; nn < 8; nn++) {
                    const float* bp = Xs + (c0k + tig) * X_STRIDE + pix0 + nn * 8 + g + dxi;
                    uint32_t b0 = __float_as_uint(bp[0]);
                    uint32_t b1 = __float_as_uint(bp[4 * X_STRIDE]);
                    mma8(c[0][nn], a[0], b0, b1);
                    mma8(c[1][nn], a[1], b0, b1);
                }
            }
        }

        if (pre) {
            float* Xs = (float*)(dyn + XOFF(p ^ 1));
            #pragma unroll
            for (int i = 0; i < 9; i++) {
                int j = l16 + i * 16;
                if (j < 130) Xs[cc * X_STRIDE + j] = __uint_as_float(f2tf32(xr[i]));
            }
        }
        asm volatile("cp.async.wait_group 0;" ::: "memory");
        __syncthreads();
    }

    // ---------------- epilogue ----------------
    // smem reuse: hs = fp16 f tile [128 oc][136 halves] (34816 B), att_part after it.
    __half* hs = (__half*)dyn;
    float* att_part = (float*)(dyn + 34816);

    float bf[2][2], aw[2][2];
    #pragma unroll
    for (int mm = 0; mm < 2; mm++)
        #pragma unroll
        for (int i2 = 0; i2 < 2; i2++) {
            int ocr = oc0 + mm * 16 + g + i2 * 8;
            bf[mm][i2] = g_bfold[ocr];
            aw[mm][i2] = g_attw[ocr];
        }

    float ap_loc[8][2];
    #pragma unroll
    for (int nn = 0; nn < 8; nn++) { ap_loc[nn][0] = 0.f; ap_loc[nn][1] = 0.f; }

    #pragma unroll
    for (int mm = 0; mm < 2; mm++)
        #pragma unroll
        for (int i2 = 0; i2 < 2; i2++) {
            int ocr = oc0 + mm * 16 + g + i2 * 8;
            __half* hrow = hs + ocr * HS_STRIDE + pix0 + 2 * tig;
            #pragma unroll
            for (int nn = 0; nn < 8; nn++) {
                float f0 = c[mm][nn][i2 * 2 + 0] + bf[mm][i2];
                float f1 = c[mm][nn][i2 * 2 + 1] + bf[mm][i2];
                ap_loc[nn][0] = fmaf(aw[mm][i2], f0, ap_loc[nn][0]);
                ap_loc[nn][1] = fmaf(aw[mm][i2], f1, ap_loc[nn][1]);
                *(__half2*)(hrow + nn * 8) = __floats2half2_rn(f0, f1);
            }
        }

    // reduce attention partials over g-lanes (same tig), deterministic butterfly
    #pragma unroll
    for (int nn = 0; nn < 8; nn++)
        #pragma unroll
        for (int j = 0; j < 2; j++) {
            float v = ap_loc[nn][j];
            v += __shfl_xor_sync(0xFFFFFFFF, v, 4);
            v += __shfl_xor_sync(0xFFFFFFFF, v, 8);
            v += __shfl_xor_sync(0xFFFFFFFF, v, 16);
            ap_loc[nn][j] = v;
        }
    if (g == 0) {
        #pragma unroll
        for (int nn = 0; nn < 8; nn++) {
            att_part[w * 64 + nn * 8 + 2 * tig + 0] = ap_loc[nn][0];
            att_part[w * 64 + nn * 8 + 2 * tig + 1] = ap_loc[nn][1];
        }
    }
    __syncthreads();

    // attention logit -> g_att
    {
        int branch = tid >> 7;
        int pix = tid & 127;
        int nh = pix >> 6, pl = pix & 63;
        float ssum = att_part[(4 * branch + nh) * 64 + pl]
                   + att_part[(4 * branch + 2 + nh) * 64 + pl];
        int xx = c0 + pix;
        float gh = fabsf((float)y  - 127.5f) * (1.f / 128.f);
        float gw = fabsf((float)xx - 127.5f) * (1.f / 128.f);
        const float* awp = branch ? attbw : attaw;
        float pre = ssum + awp[64] * gh + awp[65] * gw + (branch ? attbb[0] : attab[0]);
        float gm = branch ? abgb[0] : abga[0];
        float bt = branch ? abbb[0] : abba[0];
        float mn = branch ? abmb[0] : abma[0];
        float vr = branch ? abvb[0] : abva[0];
        float av = (pre - mn) * gm / sqrtf(vr + 1e-5f) + bt;
        g_att[(((size_t)branch * BB + b) * HH + y) * WW + xx] = av;
    }

    // coalesced fp16 f store: each oc row = 256B = 16 lanes x 16B
    #pragma unroll
    for (int it = 0; it < 8; it++) {
        int lin = it * 256 + tid;
        int oc = lin >> 4;
        int seg = lin & 15;
        uint4 v = *(const uint4*)(hs + oc * HS_STRIDE + seg * 8);
        *(uint4*)(g_fh + (((size_t)b * NOC + oc) * HH + y) * WW + c0 + seg * 8) = v;
    }
}

// ---------------- kernel 2: 3x3 attention conv + sigmoid + gated store ----------------
__global__ void __launch_bounds__(256) map_kernel(
    float* __restrict__ out,
    const float* __restrict__ wa, const float* __restrict__ wb,
    const float* __restrict__ s1, const float* __restrict__ s2)
{
    __shared__ float swa[36], swb[36];
    int t = threadIdx.y * 32 + threadIdx.x;
    if (t < 36) { swa[t] = wa[t]; swb[t] = wb[t]; }
    __syncthreads();

    int b   = blockIdx.z;
    int gy  = blockIdx.y * 8 + threadIdx.y;
    int gx4 = blockIdx.x * 128 + threadIdx.x * 4;

    const float prmax = 1.41421356237f * (127.5f / 128.f);
    const float prmin = 1.41421356237f * (0.5f / 128.f);
    const float prk = 2.f / (prmax - prmin);
    const float prc = 1.f - prmax * prk;

    float scl1 = s1[0], scl2 = s2[0];
    float mapa[4], mapb[4];
    #pragma unroll
    for (int p = 0; p < 4; p++) {
        int gx = gx4 + p;
        float sa = 0.f, sb = 0.f;
        #pragma unroll
        for (int rr = 0; rr < 3; rr++) {
            int yq = gy + rr - 1;
            if ((unsigned)yq >= HH) continue;
            #pragma unroll
            for (int ss = 0; ss < 3; ss++) {
                int xq = gx + ss - 1;
                if ((unsigned)xq >= WW) continue;
                float av = g_att[(((size_t)0 * BB + b) * HH + yq) * WW + xq];
                float bv = g_att[(((size_t)1 * BB + b) * HH + yq) * WW + xq];
                float gh = fabsf((float)yq - 127.5f) * (1.f / 128.f);
                float gw = fabsf((float)xq - 127.5f) * (1.f / 128.f);
                float pr = prk * sqrtf(gh * gh + gw * gw) + prc;
                int tap = rr * 3 + ss;
                sa += swa[tap] * av + swa[9 + tap] * gh + swa[18 + tap] * gw + swa[27 + tap] * pr;
                sb += swb[tap] * bv + swb[9 + tap] * gh + swb[18 + tap] * gw + swb[27 + tap] * pr;
            }
        }
        mapa[p] = scl1 / (1.f + expf(-sa));
        mapb[p] = scl2 / (1.f + expf(-sb));
    }

    size_t base = (((size_t)b * NOC) * HH + gy) * WW + gx4;
    #pragma unroll 4
    for (int oc = 0; oc < NOC; oc++) {
        uint2 raw = *(const uint2*)(g_fh + base + (size_t)oc * HH * WW);
        __half2 h01 = *reinterpret_cast<__half2*>(&raw.x);
        __half2 h23 = *reinterpret_cast<__half2*>(&raw.y);
        float2 f01 = __half22float2(h01);
        float2 f23 = __half22float2(h23);
        float4 v;
        if (oc < 64) {
            v.x = f01.x * mapa[0]; v.y = f01.y * mapa[1];
            v.z = f23.x * mapa[2]; v.w = f23.y * mapa[3];
        } else {
            v.x = f01.x * mapb[0]; v.y = f01.y * mapb[1];
            v.z = f23.x * mapb[2]; v.w = f23.y * mapb[3];
        }
        *(float4*)(out + base + (size_t)oc * HH * WW) = v;
    }
}

// ---------------- launch ----------------
extern "C" void kernel_launch(void* const* d_in, const int* in_sizes, int n_in,
                              void* d_out, int out_size)
{
    const float* x     = (const float*)d_in[0];
    const float* caw   = (const float*)d_in[1];
    const float* cab   = (const float*)d_in[2];
    const float* cbw   = (const float*)d_in[3];
    const float* cbb   = (const float*)d_in[4];
    const float* bag   = (const float*)d_in[5];
    const float* babt  = (const float*)d_in[6];
    const float* bam   = (const float*)d_in[7];
    const float* bav   = (const float*)d_in[8];
    const float* bbg   = (const float*)d_in[9];
    const float* bbbt  = (const float*)d_in[10];
    const float* bbm   = (const float*)d_in[11];
    const float* bbv   = (const float*)d_in[12];
    const float* attaw = (const float*)d_in[13];
    const float* attab = (const float*)d_in[14];
    const float* attbw = (const float*)d_in[15];
    const float* attbb = (const float*)d_in[16];
    const float* abga  = (const float*)d_in[17];
    const float* abba  = (const float*)d_in[18];
    const float* abma  = (const float*)d_in[19];
    const float* abva  = (const float*)d_in[20];
    const float* abgb  = (const float*)d_in[21];
    const float* abbb  = (const float*)d_in[22];
    const float* abmb  = (const float*)d_in[23];
    const float* abvb  = (const float*)d_in[24];
    const float* anaw  = (const float*)d_in[25];
    const float* anbw  = (const float*)d_in[26];
    const float* s1    = (const float*)d_in[27];
    const float* s2    = (const float*)d_in[28];
    float* out = (float*)d_out;

    cudaFuncSetAttribute(conv_att_kernel,
                         cudaFuncAttributeMaxDynamicSharedMemorySize, DYN_BYTES);

    setup_kernel<<<(NSTAGE * A_FLOATS + 255) / 256, 256>>>(
        caw, cab, cbw, cbb,
        bag, babt, bam, bav, bbg, bbbt, bbm, bbv,
        attaw, attbw);

    conv_att_kernel<<<dim3(2, HH, BB), 256, DYN_BYTES>>>(
        x, attaw, attab, attbw, attbb,
        abga, abba, abma, abva, abgb, abbb, abmb, abvb);

    map_kernel<<<dim3(WW / 128, HH / 8, BB), dim3(32, 8)>>>(
        out, anaw, anbw, s1, s2);
}